// round 4
// baseline (speedup 1.0000x reference)
#include <cuda_runtime.h>

#define TT 11
#define THREADS 256
#define ITEMS 16
#define PER_BLOCK 4096
#define BMAX 8192

__device__ int g_blockHist[BMAX * 16];
__device__ int g_blockBase[BMAX * 16];   // includes type offset after k_scanoff

// field extraction from 10-bit packed counters (types 0..5 in q0, 6..10 in q1)
__device__ __forceinline__ int fieldOf(unsigned long long q0, unsigned long long q1, int t) {
    unsigned long long q = (t < 6) ? q0 : q1;
    int sh = (t < 6) ? 10 * t : 10 * (t - 6);
    return (int)((q >> sh) & 1023ull);
}

// per-block dtype detection: read 256 int64 words; if data is int32 the hi half
// of each word is the next type value (nonzero w.p. 10/11 per sample).
__device__ __forceinline__ int detect64(const void* types, int N, int base) {
    const long long* t64 = (const long long*)types;
    int wmax = N >> 1;
    int wi = (base >> 1) + threadIdx.x;
    if (wi >= wmax) wi = wmax - 1;
    long long v = t64[wi];
    return __syncthreads_and(v >= 0 && v < TT);
}

__device__ __forceinline__ void loadTypes16(const void* types, int gbase, int is64,
                                            unsigned int tp[4]) {
    if (is64) {
        const longlong2* p = (const longlong2*)((const long long*)types + gbase);
#pragma unroll
        for (int k = 0; k < 4; k++) {
            longlong2 a = p[2 * k], b = p[2 * k + 1];
            tp[k] = (unsigned)a.x | ((unsigned)a.y << 8) |
                    ((unsigned)b.x << 16) | ((unsigned)b.y << 24);
        }
    } else {
        const int4* p = (const int4*)((const int*)types + gbase);
#pragma unroll
        for (int k = 0; k < 4; k++) {
            int4 a = p[k];
            tp[k] = (unsigned)a.x | ((unsigned)a.y << 8) |
                    ((unsigned)a.z << 16) | ((unsigned)a.w << 24);
        }
    }
}

__device__ __forceinline__ int scalarType(const void* types, int i, int is64) {
    return is64 ? (int)((const long long*)types)[i] : ((const int*)types)[i];
}

// -------- pass 1: per-block histogram (register packed counters, no atomics) -----
__global__ void __launch_bounds__(THREADS) k_hist(const void* __restrict__ types, int N) {
    __shared__ unsigned long long sW0[8], sW1[8];
    int tid = threadIdx.x, lane = tid & 31, w = tid >> 5;
    int base = blockIdx.x * PER_BLOCK;
    int is64 = detect64(types, N, base);

    int myBase = base + tid * ITEMS;
    unsigned long long p0 = 0, p1 = 0;
    if (base + PER_BLOCK <= N) {
        unsigned tp[4];
        loadTypes16(types, myBase, is64, tp);
#pragma unroll
        for (int j = 0; j < ITEMS; j++) {
            int t = (tp[j >> 2] >> ((j & 3) * 8)) & 0xFF;
            if (t < 6) p0 += 1ull << (10 * t); else p1 += 1ull << (10 * (t - 6));
        }
    } else {
        int cnt = N - myBase; cnt = cnt < 0 ? 0 : (cnt > ITEMS ? ITEMS : cnt);
        for (int j = 0; j < cnt; j++) {
            int t = scalarType(types, myBase + j, is64);
            if (t < 6) p0 += 1ull << (10 * t); else p1 += 1ull << (10 * (t - 6));
        }
    }
#pragma unroll
    for (int d = 16; d; d >>= 1) {
        p0 += __shfl_xor_sync(0xffffffffu, p0, d);
        p1 += __shfl_xor_sync(0xffffffffu, p1, d);
    }
    if (lane == 0) { sW0[w] = p0; sW1[w] = p1; }
    __syncthreads();
    if (tid < TT) {
        int s = 0;
#pragma unroll
        for (int ww = 0; ww < 8; ww++) s += fieldOf(sW0[ww], sW1[ww], tid);
        g_blockHist[blockIdx.x * 16 + tid] = s;
    }
}

// -------- pass 2 (fused): per-type scan over blocks, fold in type offsets --------
__global__ void k_scanoff(int B, float* outTail, int writeTail) {
    __shared__ int sCounts[16], sOff[16];
    int tid = threadIdx.x, w = tid >> 5, lane = tid & 31;
    int chunk = (B + 31) / 32;
    int s0 = lane * chunk;
    int cnt = B - s0; cnt = cnt < 0 ? 0 : (cnt > chunk ? chunk : cnt);
    int excl = 0;
    if (w < TT) {
        int sum = 0;
        for (int j = 0; j < cnt; j++) sum += g_blockHist[(s0 + j) * 16 + w];
        int inc = sum;
#pragma unroll
        for (int d = 1; d < 32; d <<= 1) {
            int n = __shfl_up_sync(0xffffffffu, inc, d);
            if (lane >= d) inc += n;
        }
        excl = inc - sum;
        if (lane == 31) sCounts[w] = inc;
    }
    __syncthreads();
    if (tid == 0) {
        int run = 0;
        for (int t = 0; t < TT; t++) {
            int c = sCounts[t];
            sOff[t] = run;
            if (writeTail) { outTail[t] = (float)c; outTail[TT + t] = (float)run; }
            run += c;
        }
    }
    __syncthreads();
    if (w < TT) {
        int run = sOff[w] + excl;   // global base for this type at this lane's chunk
        for (int j = 0; j < cnt; j++) {
            int v = g_blockHist[(s0 + j) * 16 + w];   // L2 hit
            g_blockBase[(s0 + j) * 16 + w] = run;
            run += v;
        }
    }
}

// -------- pass 3: register-only stable rank + smem staging + coalesced copy ------
__global__ void __launch_bounds__(THREADS, 4) k_scatter(const float* __restrict__ coords,
                                                        const void* __restrict__ types,
                                                        float* __restrict__ out, int N) {
    extern __shared__ char smem[];
    unsigned long long* sW0 = (unsigned long long*)smem;       // 8 ULL @0 (8B aligned!)
    unsigned long long* sW1 = sW0 + 8;                         // 8 ULL @64
    float* sC = (float*)(sW1 + 8);                             // 4096*3 floats @128
    int* sWB = (int*)(sC + PER_BLOCK * 3);                     // 8*16
    int* sTot = sWB + 128;                                     // 16
    int* sLto = sTot + 16;                                     // 16
    // total: 128 + 49152 + 512 + 64 + 64 = 49920 bytes

    int tid = threadIdx.x, lane = tid & 31, w = tid >> 5;
    int blk = blockIdx.x, base = blk * PER_BLOCK;
    int nblk = min(PER_BLOCK, N - base);
    int is64 = detect64(types, N, base);

    int myBase = tid * ITEMS;
    int myCnt = nblk - myBase; myCnt = myCnt < 0 ? 0 : (myCnt > ITEMS ? ITEMS : myCnt);
    bool full = (myCnt == ITEMS);

    // types -> 4 packed-byte registers
    unsigned tp[4];
    if (full) {
        loadTypes16(types, base + myBase, is64, tp);
    } else {
        tp[0] = tp[1] = tp[2] = tp[3] = 0;
        for (int j = 0; j < myCnt; j++)
            tp[j >> 2] |= (unsigned)scalarType(types, base + myBase + j, is64) << ((j & 3) * 8);
    }

    // per-thread packed histogram
    unsigned long long p0 = 0, p1 = 0;
#pragma unroll
    for (int j = 0; j < ITEMS; j++) {
        if (j < myCnt) {
            int t = (tp[j >> 2] >> ((j & 3) * 8)) & 0xFF;
            if (t < 6) p0 += 1ull << (10 * t); else p1 += 1ull << (10 * (t - 6));
        }
    }
    unsigned long long m0 = p0, m1 = p1;
#pragma unroll
    for (int d = 1; d < 32; d <<= 1) {
        unsigned long long n0 = __shfl_up_sync(0xffffffffu, p0, d);
        unsigned long long n1 = __shfl_up_sync(0xffffffffu, p1, d);
        if (lane >= d) { p0 += n0; p1 += n1; }
    }
    unsigned long long e0 = p0 - m0, e1 = p1 - m1;   // exclusive within warp
    if (lane == 31) { sW0[w] = p0; sW1[w] = p1; }
    __syncthreads();
    if (tid < TT) {
        int run = 0;
#pragma unroll
        for (int ww = 0; ww < 8; ww++) {
            sWB[ww * 16 + tid] = run;
            run += fieldOf(sW0[ww], sW1[ww], tid);
        }
        sTot[tid] = run;
    }
    __syncthreads();
    if (tid == 0) {
        int run = 0;
        for (int t = 0; t < TT; t++) { sLto[t] = run; run += sTot[t]; }
    }
    __syncthreads();

    // per-thread per-type start positions packed into 16-bit fields (3 ULLs)
    unsigned long long b0 = 0, b1 = 0, b2 = 0;
#pragma unroll
    for (int t = 0; t < TT; t++) {
        unsigned long long val =
            (unsigned long long)(sLto[t] + sWB[w * 16 + t] + fieldOf(e0, e1, t));
        if (t < 4)      b0 |= val << (16 * t);
        else if (t < 8) b1 |= val << (16 * (t - 4));
        else            b2 |= val << (16 * (t - 8));
    }

    // replay in 4 chunks of 4 items: just-in-time coord loads (12 live regs),
    // rank computed purely in registers (no LDS dependency chain).
    unsigned long long qq0 = 0, qq1 = 0;
#pragma unroll
    for (int c = 0; c < 4; c++) {
        float cz[12];
        if (full) {
            const float4* cp = (const float4*)(coords + (size_t)3 * (base + myBase) + 12 * c);
            float4 v0 = cp[0], v1 = cp[1], v2 = cp[2];
            cz[0] = v0.x; cz[1] = v0.y; cz[2] = v0.z; cz[3] = v0.w;
            cz[4] = v1.x; cz[5] = v1.y; cz[6] = v1.z; cz[7] = v1.w;
            cz[8] = v2.x; cz[9] = v2.y; cz[10] = v2.z; cz[11] = v2.w;
        } else {
            const float* cp = coords + (size_t)3 * (base + myBase) + 12 * c;
            int avail = 3 * myCnt - 12 * c;
#pragma unroll
            for (int i = 0; i < 12; i++) cz[i] = (i < avail) ? cp[i] : 0.0f;
        }
#pragma unroll
        for (int j2 = 0; j2 < 4; j2++) {
            int j = 4 * c + j2;
            if (j < myCnt) {
                int t = (tp[j >> 2] >> ((j & 3) * 8)) & 0xFF;
                int sh10 = (t < 6) ? 10 * t : 10 * (t - 6);
                unsigned long long qq = (t < 6) ? qq0 : qq1;
                int cnt = (int)((qq >> sh10) & 1023ull);
                unsigned long long bb = (t < 4) ? b0 : ((t < 8) ? b1 : b2);
                int bval = (int)((bb >> (16 * (t & 3))) & 0xFFFFull);
                int r = bval + cnt;
                if (t < 6) qq0 += 1ull << sh10; else qq1 += 1ull << sh10;
                sC[3 * r + 0] = cz[3 * j2 + 0];
                sC[3 * r + 1] = cz[3 * j2 + 1];
                sC[3 * r + 2] = cz[3 * j2 + 2];
            }
        }
    }
    __syncthreads();

    // coalesced copy-out, one contiguous segment per type
    for (int t = 0; t < TT; t++) {
        int cnt3 = sTot[t] * 3;
        size_t gb = (size_t)g_blockBase[blk * 16 + t] * 3;  // includes type offset
        int sb = sLto[t] * 3;
        for (int i = tid; i < cnt3; i += THREADS)
            out[gb + i] = sC[sb + i];
    }
}

extern "C" void kernel_launch(void* const* d_in, const int* in_sizes, int n_in,
                              void* d_out, int out_size) {
    const float* coords = (const float*)d_in[0];
    const void* types = d_in[1];
    int N = in_sizes[1];
    int B = (N + PER_BLOCK - 1) / PER_BLOCK;
    float* out = (float*)d_out;
    long long coordsOut = (long long)3 * N;
    int writeTail = ((long long)out_size >= coordsOut + 2 * TT) ? 1 : 0;

    const int SMEM = 49920;
    cudaFuncSetAttribute(k_scatter, cudaFuncAttributeMaxDynamicSharedMemorySize, SMEM);

    k_hist<<<B, THREADS>>>(types, N);
    k_scanoff<<<1, 352>>>(B, out + coordsOut, writeTail);
    k_scatter<<<B, THREADS, SMEM>>>(coords, types, out, N);
}

// round 5
// speedup vs baseline: 1.1213x; 1.1213x over previous
#include <cuda_runtime.h>

#define TT 11
#define THREADS 256
#define ITEMS 16
#define PER_BLOCK 4096
#define BMAX 8192

__device__ int g_blockHist[BMAX * 16];
__device__ int g_blockBase[BMAX * 16];   // includes type offset after scan
__device__ unsigned int g_ticket;        // zero-init; reset by scanning block

// field extraction from 10-bit packed counters (types 0..5 in q0, 6..10 in q1)
__device__ __forceinline__ int fieldOf(unsigned long long q0, unsigned long long q1, int t) {
    unsigned long long q = (t < 6) ? q0 : q1;
    int sh = (t < 6) ? 10 * t : 10 * (t - 6);
    return (int)((q >> sh) & 1023ull);
}

// per-block dtype detection: read 256 int64 words; if data is int32 the hi half
// of each word is the next type value (nonzero w.p. 10/11 per sample).
__device__ __forceinline__ int detect64(const void* types, int N, int base) {
    const long long* t64 = (const long long*)types;
    int wmax = N >> 1;
    int wi = (base >> 1) + threadIdx.x;
    if (wi >= wmax) wi = wmax - 1;
    long long v = t64[wi];
    return __syncthreads_and(v >= 0 && v < TT);
}

__device__ __forceinline__ void loadTypes16(const void* types, int gbase, int is64,
                                            unsigned int tp[4]) {
    if (is64) {
        const longlong2* p = (const longlong2*)((const long long*)types + gbase);
#pragma unroll
        for (int k = 0; k < 4; k++) {
            longlong2 a = p[2 * k], b = p[2 * k + 1];
            tp[k] = (unsigned)a.x | ((unsigned)a.y << 8) |
                    ((unsigned)b.x << 16) | ((unsigned)b.y << 24);
        }
    } else {
        const int4* p = (const int4*)((const int*)types + gbase);
#pragma unroll
        for (int k = 0; k < 4; k++) {
            int4 a = p[k];
            tp[k] = (unsigned)a.x | ((unsigned)a.y << 8) |
                    ((unsigned)a.z << 16) | ((unsigned)a.w << 24);
        }
    }
}

__device__ __forceinline__ int scalarType(const void* types, int i, int is64) {
    return is64 ? (int)((const long long*)types)[i] : ((const int*)types)[i];
}

// -------- pass 1: per-block histogram; LAST block performs the global scan ------
__global__ void __launch_bounds__(THREADS) k_histscan(const void* __restrict__ types,
                                                      int N, int B,
                                                      float* outTail, int writeTail) {
    __shared__ unsigned long long sW0[8], sW1[8];
    __shared__ int sCounts[16], sOff[16], sExcl[TT * 32];
    __shared__ int sIsLast;
    int tid = threadIdx.x, lane = tid & 31, w = tid >> 5;
    int base = blockIdx.x * PER_BLOCK;
    int is64 = detect64(types, N, base);

    int myBase = base + tid * ITEMS;
    unsigned long long p0 = 0, p1 = 0;
    if (base + PER_BLOCK <= N) {
        unsigned tp[4];
        loadTypes16(types, myBase, is64, tp);
#pragma unroll
        for (int j = 0; j < ITEMS; j++) {
            int t = (tp[j >> 2] >> ((j & 3) * 8)) & 0xFF;
            if (t < 6) p0 += 1ull << (10 * t); else p1 += 1ull << (10 * (t - 6));
        }
    } else {
        int cnt = N - myBase; cnt = cnt < 0 ? 0 : (cnt > ITEMS ? ITEMS : cnt);
        for (int j = 0; j < cnt; j++) {
            int t = scalarType(types, myBase + j, is64);
            if (t < 6) p0 += 1ull << (10 * t); else p1 += 1ull << (10 * (t - 6));
        }
    }
#pragma unroll
    for (int d = 16; d; d >>= 1) {
        p0 += __shfl_xor_sync(0xffffffffu, p0, d);
        p1 += __shfl_xor_sync(0xffffffffu, p1, d);
    }
    if (lane == 0) { sW0[w] = p0; sW1[w] = p1; }
    __syncthreads();
    if (tid < TT) {
        int s = 0;
#pragma unroll
        for (int ww = 0; ww < 8; ww++) s += fieldOf(sW0[ww], sW1[ww], tid);
        g_blockHist[blockIdx.x * 16 + tid] = s;
    }
    __syncthreads();
    if (tid == 0) {
        __threadfence();
        unsigned tk = atomicAdd(&g_ticket, 1u);
        sIsLast = (tk == (unsigned)(B - 1));
    }
    __syncthreads();
    if (!sIsLast) return;

    // ---- last-arriving block: global per-type scan over all blocks ----
    __threadfence();   // acquire: make other blocks' hist writes visible
    int chunk = (B + 31) / 32;
    int s0 = lane * chunk;
    int cnt = B - s0; cnt = cnt < 0 ? 0 : (cnt > chunk ? chunk : cnt);
    for (int tt = w; tt < TT; tt += 8) {
        int sum = 0;
        for (int j = 0; j < cnt; j++) sum += g_blockHist[(s0 + j) * 16 + tt];
        int inc = sum;
#pragma unroll
        for (int d = 1; d < 32; d <<= 1) {
            int n = __shfl_up_sync(0xffffffffu, inc, d);
            if (lane >= d) inc += n;
        }
        sExcl[tt * 32 + lane] = inc - sum;
        if (lane == 31) sCounts[tt] = inc;
    }
    __syncthreads();
    if (tid == 0) {
        int run = 0;
        for (int t = 0; t < TT; t++) {
            int c = sCounts[t];
            sOff[t] = run;
            if (writeTail) { outTail[t] = (float)c; outTail[TT + t] = (float)run; }
            run += c;
        }
        g_ticket = 0;   // reset for next graph replay
    }
    __syncthreads();
    for (int tt = w; tt < TT; tt += 8) {
        int run = sOff[tt] + sExcl[tt * 32 + lane];
        for (int j = 0; j < cnt; j++) {
            int v = g_blockHist[(s0 + j) * 16 + tt];   // L2 hit
            g_blockBase[(s0 + j) * 16 + tt] = run;
            run += v;
        }
    }
}

// -------- pass 2: LDS stable rank + smem staging + dense monotonic copy-out -----
__global__ void __launch_bounds__(THREADS, 3) k_scatter(const float* __restrict__ coords,
                                                        const void* __restrict__ types,
                                                        float* __restrict__ out, int N) {
    extern __shared__ char smem[];
    unsigned long long* sW0 = (unsigned long long*)smem;       // 8 ULL @0 (8B aligned)
    unsigned long long* sW1 = sW0 + 8;                         // 8 ULL @64
    float* sC = (float*)(sW1 + 8);                             // 4096*3 floats @128
    int* sCnt = (int*)(sC + PER_BLOCK * 3);                    // TT*257
    int* sWB = sCnt + TT * 257;                                // 8*16
    int* sTot = sWB + 128;                                     // 16
    int* sB3 = sTot + 16;                                      // 12 (segment bounds *3)
    int* sGB3 = sB3 + 12;                                      // 11 (global bases *3)
    // total ~61.4 KB

    int tid = threadIdx.x, lane = tid & 31, w = tid >> 5;
    int blk = blockIdx.x, base = blk * PER_BLOCK;
    int nblk = min(PER_BLOCK, N - base);
    int is64 = detect64(types, N, base);

    if (tid < TT) sGB3[tid] = g_blockBase[blk * 16 + tid] * 3;

    int myBase = tid * ITEMS;
    int myCnt = nblk - myBase; myCnt = myCnt < 0 ? 0 : (myCnt > ITEMS ? ITEMS : myCnt);
    bool full = (myCnt == ITEMS);

    // types -> 4 packed-byte registers
    unsigned tp[4];
    if (full) {
        loadTypes16(types, base + myBase, is64, tp);
    } else {
        tp[0] = tp[1] = tp[2] = tp[3] = 0;
        for (int j = 0; j < myCnt; j++)
            tp[j >> 2] |= (unsigned)scalarType(types, base + myBase + j, is64) << ((j & 3) * 8);
    }

    // per-thread packed histogram
    unsigned long long p0 = 0, p1 = 0;
#pragma unroll
    for (int j = 0; j < ITEMS; j++) {
        if (j < myCnt) {
            int t = (tp[j >> 2] >> ((j & 3) * 8)) & 0xFF;
            if (t < 6) p0 += 1ull << (10 * t); else p1 += 1ull << (10 * (t - 6));
        }
    }
    unsigned long long m0 = p0, m1 = p1;
#pragma unroll
    for (int d = 1; d < 32; d <<= 1) {
        unsigned long long n0 = __shfl_up_sync(0xffffffffu, p0, d);
        unsigned long long n1 = __shfl_up_sync(0xffffffffu, p1, d);
        if (lane >= d) { p0 += n0; p1 += n1; }
    }
    unsigned long long e0 = p0 - m0, e1 = p1 - m1;   // exclusive within warp
    if (lane == 31) { sW0[w] = p0; sW1[w] = p1; }
    __syncthreads();
    if (tid < TT) {
        int run = 0;
#pragma unroll
        for (int ww = 0; ww < 8; ww++) {
            sWB[ww * 16 + tid] = run;
            run += fieldOf(sW0[ww], sW1[ww], tid);
        }
        sTot[tid] = run;
    }
    __syncthreads();
    if (tid == 0) {
        int run = 0;
        for (int t = 0; t < TT; t++) { sB3[t] = 3 * run; run += sTot[t]; }
        sB3[TT] = 3 * run;
    }
    __syncthreads();

    // per-thread per-type start slots into LDS table (stride 257 spreads banks)
#pragma unroll
    for (int t = 0; t < TT; t++)
        sCnt[t * 257 + tid] = sB3[t] / 3 + sWB[w * 16 + t] + fieldOf(e0, e1, t);
    __syncthreads();

    // replay in 4 chunks of 4 items: JIT coord loads (12 live regs),
    // stable LDS-rank placement into shared, grouped by type.
#pragma unroll
    for (int c = 0; c < 4; c++) {
        float cz[12];
        if (full) {
            const float4* cp = (const float4*)(coords + (size_t)3 * (base + myBase) + 12 * c);
            float4 v0 = cp[0], v1 = cp[1], v2 = cp[2];
            cz[0] = v0.x; cz[1] = v0.y; cz[2] = v0.z; cz[3] = v0.w;
            cz[4] = v1.x; cz[5] = v1.y; cz[6] = v1.z; cz[7] = v1.w;
            cz[8] = v2.x; cz[9] = v2.y; cz[10] = v2.z; cz[11] = v2.w;
        } else {
            const float* cp = coords + (size_t)3 * (base + myBase) + 12 * c;
            int avail = 3 * myCnt - 12 * c;
#pragma unroll
            for (int i = 0; i < 12; i++) cz[i] = (i < avail) ? cp[i] : 0.0f;
        }
#pragma unroll
        for (int j2 = 0; j2 < 4; j2++) {
            int j = 4 * c + j2;
            if (j < myCnt) {
                int t = (tp[j >> 2] >> ((j & 3) * 8)) & 0xFF;
                int idx = t * 257 + tid;
                int r = sCnt[idx];
                sCnt[idx] = r + 1;
                sC[3 * r + 0] = cz[3 * j2 + 0];
                sC[3 * r + 1] = cz[3 * j2 + 1];
                sC[3 * r + 2] = cz[3 * j2 + 2];
            }
        }
    }
    __syncthreads();

    // dense monotonic copy-out: one flat loop, type pointer advances amortized
    int tot3 = 3 * nblk;
    int t = 0;
    int nb = sB3[1];
    int sb = 0;
    int gb = sGB3[0];
    for (int i = tid; i < tot3; i += THREADS) {
        while (i >= nb) { t++; nb = sB3[t + 1]; sb = sB3[t]; gb = sGB3[t]; }
        out[(size_t)(gb + (i - sb))] = sC[i];
    }
}

extern "C" void kernel_launch(void* const* d_in, const int* in_sizes, int n_in,
                              void* d_out, int out_size) {
    const float* coords = (const float*)d_in[0];
    const void* types = d_in[1];
    int N = in_sizes[1];
    int B = (N + PER_BLOCK - 1) / PER_BLOCK;
    float* out = (float*)d_out;
    long long coordsOut = (long long)3 * N;
    int writeTail = ((long long)out_size >= coordsOut + 2 * TT) ? 1 : 0;

    const int SMEM = 61568;
    cudaFuncSetAttribute(k_scatter, cudaFuncAttributeMaxDynamicSharedMemorySize, SMEM);

    k_histscan<<<B, THREADS>>>(types, N, B, out + coordsOut, writeTail);
    k_scatter<<<B, THREADS, SMEM>>>(coords, types, out, N);
}